// round 1
// baseline (speedup 1.0000x reference)
#include <cuda_runtime.h>

// NT-Xent loss, fused single pass.
// inp: (C=8, V=2, B=4096, D=512) fp32, flat index ((c*2+v)*4096 + b)*512 + d.
// For each b: 16 vectors; anchors = v==0 rows. G[i][k] = <x[2i], x[k]>.
// sim = G / (max(|xi|,eps)*max(|xk|,eps)) * (1/T); pos = sim[2i+1];
// loss_i = logsumexp(pos, {sim[k] : k>>1 != i}) - pos; out = mean over (C,B).

static constexpr int   kC   = 8;
static constexpr int   kB   = 4096;
static constexpr int   kD   = 512;
static constexpr int   kNV  = 16;      // C*V
static constexpr float kInvT = 10.0f;  // 1/0.1
static constexpr float kEps  = 1e-12f;

__device__ float g_partials[kB];

__global__ __launch_bounds__(256)
void ntxent_main(const float* __restrict__ inp) {
    __shared__ float4 Xs[kNV][kD / 4];   // 16 x 128 float4 = 32 KB
    __shared__ float  s_norm[kNV];
    __shared__ float  s_G[kC][kNV];

    const int b    = blockIdx.x;
    const int tid  = threadIdx.x;
    const int w    = tid >> 5;
    const int lane = tid & 31;

    // ---- load 16x512 tile + fused sum-of-squares (warp w loads rows 2w, 2w+1) ----
    #pragma unroll
    for (int r = 0; r < 2; r++) {
        const int row = 2 * w + r;
        const float4* src = reinterpret_cast<const float4*>(inp)
                          + ((size_t)row * kB + b) * (kD / 4);
        float ss = 0.f;
        #pragma unroll
        for (int t = 0; t < 4; t++) {
            float4 x = src[lane + 32 * t];
            Xs[row][lane + 32 * t] = x;
            ss = fmaf(x.x, x.x, fmaf(x.y, x.y, fmaf(x.z, x.z, fmaf(x.w, x.w, ss))));
        }
        #pragma unroll
        for (int off = 16; off > 0; off >>= 1)
            ss += __shfl_xor_sync(0xffffffffu, ss, off);
        if (lane == 0) s_norm[row] = sqrtf(ss);
    }
    __syncthreads();

    // ---- Gram tile: warp w -> crops {c0, c1} x columns [jbase, jbase+8) ----
    const int c0    = 2 * (w & 3);
    const int c1    = c0 + 1;
    const int jbase = (w >> 2) * 8;

    float v[16];
    #pragma unroll
    for (int k = 0; k < 16; k++) v[k] = 0.f;

    #pragma unroll
    for (int t = 0; t < 4; t++) {
        const float4 a0 = Xs[2 * c0][lane + 32 * t];   // anchor row of crop c0 (v=0)
        const float4 a1 = Xs[2 * c1][lane + 32 * t];   // anchor row of crop c1
        #pragma unroll
        for (int j = 0; j < 8; j++) {
            const float4 x = Xs[jbase + j][lane + 32 * t];
            v[j]     = fmaf(a0.x, x.x, fmaf(a0.y, x.y, fmaf(a0.z, x.z, fmaf(a0.w, x.w, v[j]))));
            v[8 + j] = fmaf(a1.x, x.x, fmaf(a1.y, x.y, fmaf(a1.z, x.z, fmaf(a1.w, x.w, v[8 + j]))));
        }
    }

    // ---- folded butterfly: 16 lane-partial accumulators -> 16 warp sums, 17 SHFL total ----
    #pragma unroll
    for (int stage = 0; stage < 4; stage++) {
        const int  off = 16 >> stage;       // 16, 8, 4, 2
        const int  nv  = 8 >> stage;        // values kept per lane after this stage
        const bool hi  = (lane & off) != 0;
        #pragma unroll
        for (int k = 0; k < nv; k++) {
            const float mine = hi ? v[k + nv] : v[k];
            const float send = hi ? v[k]      : v[k + nv];
            v[k] = mine + __shfl_xor_sync(0xffffffffu, send, off);
        }
    }
    v[0] += __shfl_xor_sync(0xffffffffu, v[0], 1);
    {
        const int idx = ((lane >> 4) & 1) * 8 + ((lane >> 3) & 1) * 4
                      + ((lane >> 2) & 1) * 2 + ((lane >> 1) & 1);
        if ((lane & 1) == 0) {
            const int crop = (idx < 8) ? c0 : c1;
            s_G[crop][jbase + (idx & 7)] = v[0];
        }
    }
    __syncthreads();

    // ---- epilogue: warp 0, lane i handles crop i ----
    if (w == 0) {
        float loss = 0.f;
        if (lane < kC) {
            const int   i  = lane;
            const float ni = fmaxf(s_norm[2 * i], kEps);
            float sim[16];
            #pragma unroll
            for (int k = 0; k < 16; k++) {
                const float nk = fmaxf(s_norm[k], kEps);
                sim[k] = s_G[i][k] / (ni * nk) * kInvT;
            }
            const float pos = sim[2 * i + 1];
            float m = pos;
            #pragma unroll
            for (int k = 0; k < 16; k++)
                if ((k >> 1) != i) m = fmaxf(m, sim[k]);
            float s = expf(pos - m);
            #pragma unroll
            for (int k = 0; k < 16; k++)
                if ((k >> 1) != i) s += expf(sim[k] - m);
            loss = m + logf(s) - pos;
        }
        #pragma unroll
        for (int off = 16; off > 0; off >>= 1)
            loss += __shfl_xor_sync(0xffffffffu, loss, off);
        if (lane == 0) g_partials[b] = loss;
    }
}

__global__ __launch_bounds__(256)
void ntxent_reduce(float* __restrict__ out) {
    __shared__ float sm[8];
    const int tid = threadIdx.x;
    float s = 0.f;
    for (int i = tid; i < kB; i += 256) s += g_partials[i];
    #pragma unroll
    for (int off = 16; off > 0; off >>= 1)
        s += __shfl_xor_sync(0xffffffffu, s, off);
    if ((tid & 31) == 0) sm[tid >> 5] = s;
    __syncthreads();
    if (tid < 8) {
        float x = sm[tid];
        #pragma unroll
        for (int off = 4; off > 0; off >>= 1)
            x += __shfl_xor_sync(0x000000ffu, x, off);
        if (tid == 0) out[0] = x * (1.0f / (kC * (float)kB));
    }
}

extern "C" void kernel_launch(void* const* d_in, const int* in_sizes, int n_in,
                              void* d_out, int out_size) {
    (void)in_sizes; (void)n_in; (void)out_size;
    const float* inp = (const float*)d_in[0];
    ntxent_main<<<kB, 256>>>(inp);
    ntxent_reduce<<<1, 256>>>((float*)d_out);
}

// round 2
// speedup vs baseline: 1.0372x; 1.0372x over previous
#include <cuda_runtime.h>

// NT-Xent loss, fully fused, pipelined.
// inp: (C=8, V=2, B=4096, D=512) fp32. Row r = c*2+v of 16; tile per b = 16x512.
// G[i][k] = <row 2i, row k>; norms from G diagonal (even) + fused ss on odd-row load.
// sim = G * inv_i * inv_k * 10; loss_i = LSE(pos, negs) - pos; out = mean.

static constexpr int kB    = 4096;
static constexpr int kIter = 4;
static constexpr int kGrid = kB / kIter;   // 1024 CTAs
static constexpr int kTileBytes = 16 * 128 * 16;          // 32 KB per buffer
static constexpr int kSmemBytes = 2 * kTileBytes + 8 * 128 * 4 + 8 * 4 + 16 * 4 + 8 * 4 + 16;

__device__ float    g_partials[kGrid];
__device__ unsigned g_ticket;   // zero-init; reset by last CTA each launch

__global__ void __launch_bounds__(256, 3)
ntxent_fused(const float* __restrict__ inp, float* __restrict__ out)
{
    extern __shared__ char smem_raw[];
    float4 (*Xs)[16][128] = reinterpret_cast<float4 (*)[16][128]>(smem_raw);
    float*    sPart  = reinterpret_cast<float*>(smem_raw + 2 * kTileBytes); // [8][128]
    float*    sSSodd = sPart + 8 * 128;   // [8]
    float*    sInv   = sSSodd + 8;        // [16]
    float*    sLoss  = sInv + 16;         // [8]
    unsigned* sFlag  = reinterpret_cast<unsigned*>(sLoss + 8);

    const int tid  = threadIdx.x;
    const int w    = tid >> 5;
    const int lane = tid & 31;
    const int ar   = lane >> 2;   // anchor row 0..7
    const int lc   = lane & 3;    // column group 0..3

    if (tid < 8) sLoss[tid] = 0.f;

    const int b0 = blockIdx.x * kIter;
    const float4* gEven = reinterpret_cast<const float4*>(inp)
                        + ((size_t)(2 * w)     * kB + b0) * 128 + lane;
    const float4* gOdd  = reinterpret_cast<const float4*>(inp)
                        + ((size_t)(2 * w + 1) * kB + b0) * 128 + lane;

    // smem dst for even row cp.async: chunk = (lane ^ w) + 32m   (swizzle key = w)
    unsigned sEven[2];
    sEven[0] = (unsigned)__cvta_generic_to_shared(&Xs[0][2 * w][lane ^ w]);
    sEven[1] = (unsigned)__cvta_generic_to_shared(&Xs[1][2 * w][lane ^ w]);

    float4 r[2][4];

    // ---- prologue: stage tile 0 ----
    {
        #pragma unroll
        for (int m = 0; m < 4; m++)
            asm volatile("cp.async.cg.shared.global [%0], [%1], 16;"
                         :: "r"(sEven[0] + m * 512), "l"(gEven + m * 32));
        #pragma unroll
        for (int m = 0; m < 4; m++) r[0][m] = __ldcs(gOdd + m * 32);
        asm volatile("cp.async.commit_group;" ::: "memory");
    }

    #pragma unroll
    for (int it = 0; it < kIter; it++) {
        const int cur = it & 1;

        // ---- stage next tile ----
        if (it + 1 < kIter) {
            const float4* ge = gEven + (it + 1) * 128;
            const float4* go = gOdd  + (it + 1) * 128;
            #pragma unroll
            for (int m = 0; m < 4; m++)
                asm volatile("cp.async.cg.shared.global [%0], [%1], 16;"
                             :: "r"(sEven[cur ^ 1] + m * 512), "l"(ge + m * 32));
            #pragma unroll
            for (int m = 0; m < 4; m++) r[cur ^ 1][m] = __ldcs(go + m * 32);
            asm volatile("cp.async.commit_group;" ::: "memory");
        }

        // ---- odd row: STS (swizzled) + fused sum-of-squares ----
        {
            float ss = 0.f;
            #pragma unroll
            for (int m = 0; m < 4; m++) {
                float4 x = r[cur][m];
                Xs[cur][2 * w + 1][(lane ^ w) + 32 * m] = x;
                ss = fmaf(x.x, x.x, fmaf(x.y, x.y, fmaf(x.z, x.z, fmaf(x.w, x.w, ss))));
            }
            #pragma unroll
            for (int off = 16; off > 0; off >>= 1)
                ss += __shfl_xor_sync(0xffffffffu, ss, off);
            if (lane == 0) sSSodd[w] = ss;
        }

        if (it + 1 < kIter) asm volatile("cp.async.wait_group 1;" ::: "memory");
        else                asm volatile("cp.async.wait_group 0;" ::: "memory");
        __syncthreads();

        // ---- Gram: warp w owns D-slice [w*16, w*16+16) chunks; lane owns (ar, 4 cols) ----
        float a0 = 0.f, a1 = 0.f, a2 = 0.f, a3 = 0.f;
        {
            const float4* pa = &Xs[cur][2 * ar][w * 16];
            const float4* p0 = &Xs[cur][lc * 4 + 0][w * 16];
            const float4* p1 = &Xs[cur][lc * 4 + 1][w * 16];
            const float4* p2 = &Xs[cur][lc * 4 + 2][w * 16];
            const float4* p3 = &Xs[cur][lc * 4 + 3][w * 16];
            const int kx01 = lc * 2;      // swizzle key for cols lc*4, lc*4+1
            const int kx23 = lc * 2 + 1;  // swizzle key for cols lc*4+2, lc*4+3
            #pragma unroll
            for (int dd = 0; dd < 16; dd++) {
                const int ia  = dd ^ ar;
                const int i01 = dd ^ kx01;
                const int i23 = dd ^ kx23;
                float4 av = pa[ia];
                float4 x0 = p0[i01];
                float4 x1 = p1[i01];
                float4 x2 = p2[i23];
                float4 x3 = p3[i23];
                a0 = fmaf(av.x, x0.x, fmaf(av.y, x0.y, fmaf(av.z, x0.z, fmaf(av.w, x0.w, a0))));
                a1 = fmaf(av.x, x1.x, fmaf(av.y, x1.y, fmaf(av.z, x1.z, fmaf(av.w, x1.w, a1))));
                a2 = fmaf(av.x, x2.x, fmaf(av.y, x2.y, fmaf(av.z, x2.z, fmaf(av.w, x2.w, a2))));
                a3 = fmaf(av.x, x3.x, fmaf(av.y, x3.y, fmaf(av.z, x3.z, fmaf(av.w, x3.w, a3))));
            }
        }
        // partials: lane (ar, lc) of warp w -> sPart[w][ar*16 + lc*4 .. +3]
        reinterpret_cast<float4*>(&sPart[w * 128 + ar * 16 + lc * 4])[0] =
            make_float4(a0, a1, a2, a3);
        __syncthreads();

        // ---- epilogue (warps 0-3): sum partials, norms, LSE ----
        const int ei = tid >> 4;   // crop i
        const int ek = tid & 15;   // column k
        float g = 0.f;
        if (tid < 128) {
            #pragma unroll
            for (int ww = 0; ww < 8; ww++) g += sPart[ww * 128 + tid];
            if (ek == 2 * ei) sInv[ek] = 1.f / fmaxf(sqrtf(g), 1e-12f);
            if (tid < 8)      sInv[2 * tid + 1] = 1.f / fmaxf(sqrtf(sSSodd[tid]), 1e-12f);
        }
        __syncthreads();
        if (tid < 128) {
            const float sim   = g * sInv[2 * ei] * sInv[ek] * 10.f;
            const bool  valid = ((ek >> 1) != ei) || (ek == 2 * ei + 1);
            float m = valid ? sim : -1e30f;
            #pragma unroll
            for (int off = 8; off > 0; off >>= 1)
                m = fmaxf(m, __shfl_xor_sync(0xffffffffu, m, off, 16));
            float e = valid ? __expf(sim - m) : 0.f;
            #pragma unroll
            for (int off = 8; off > 0; off >>= 1)
                e += __shfl_xor_sync(0xffffffffu, e, off, 16);
            if (ek == 2 * ei + 1)               // this thread's sim == pos
                sLoss[ei] += (m + __logf(e)) - sim;
        }
        __syncthreads();   // protects Xs / sPart / sSSodd / sInv reuse next iteration
    }

    // ---- CTA partial + deterministic last-block reduction ----
    if (tid == 0) {
        float t = 0.f;
        #pragma unroll
        for (int i = 0; i < 8; i++) t += sLoss[i];
        g_partials[blockIdx.x] = t;
        __threadfence();
        unsigned tk = atomicAdd(&g_ticket, 1u);
        *sFlag = (tk == kGrid - 1) ? 1u : 0u;
    }
    __syncthreads();
    if (*sFlag) {
        float s = 0.f;
        #pragma unroll
        for (int m = 0; m < kGrid / 256; m++)
            s += __ldcg(&g_partials[tid + m * 256]);   // fixed order: deterministic
        #pragma unroll
        for (int off = 16; off > 0; off >>= 1)
            s += __shfl_xor_sync(0xffffffffu, s, off);
        if (lane == 0) sPart[w] = s;
        __syncthreads();
        if (tid == 0) {
            float tot = 0.f;
            #pragma unroll
            for (int i = 0; i < 8; i++) tot += sPart[i];
            out[0] = tot * (1.0f / (8.0f * 4096.0f));
            g_ticket = 0u;   // reset for next graph replay
        }
    }
}

extern "C" void kernel_launch(void* const* d_in, const int* in_sizes, int n_in,
                              void* d_out, int out_size) {
    (void)in_sizes; (void)n_in; (void)out_size;
    const float* inp = (const float*)d_in[0];
    cudaFuncSetAttribute(ntxent_fused, cudaFuncAttributeMaxDynamicSharedMemorySize, kSmemBytes);
    ntxent_fused<<<kGrid, 256, kSmemBytes>>>(inp, (float*)d_out);
}